// round 10
// baseline (speedup 1.0000x reference)
#include <cuda_runtime.h>
#include <cuda_bf16.h>
#include <cstdint>

// Shapes
#define M_TOTAL 10752          // B*T*N = 8*64*21
#define C_IN    128
#define F_OUT   256
#define N_SP    21
#define BM      64
#define MT      (M_TOTAL / BM) // 168 m-tiles

// --- gemm smem: A hi/lo (bf16, padded rows for conflict-free ldmatrix) ---
#define TSTR    272
#define SM_AHI  0
#define SM_ALO  (SM_AHI + 64 * TSTR)      // 17408
#define SM_TOT  (SM_ALO + 64 * TSTR)      // 34816

// --- gram smem: transposed Xs tile [c][m], 96 m padded, 208B rows ---
#define GSTR    104                        // bf16 elems/row = 208B (13*16B)
#define GSM_HI  0
#define GSM_LO  (128 * GSTR * 2)           // 26624
#define GSM_TOT (2 * 128 * GSTR * 2)       // 53248
#define GBM     84                         // 4 shift-groups per gram tile
#define GT      (M_TOTAL / GBM)            // 128 gram tiles

// Scratch (allocation-free device globals)
__device__ float g_gramP[GT * 128 * 128];    // 8 MB gram partials
__device__ float g_colP [GT * 128];          // colsum partials
__device__ float g_G[128 * 128];             // reduced Gram
__device__ float g_s[128];                   // reduced colsum
__device__ float g_scale[F_OUT];
__device__ float g_shift[F_OUT];
// W as per-lane mma B-fragments: [ft][wf][hl][ks][p][lane]
__device__ uint4 g_Bfrag[8192];              // 128 KB, L1-resident

__device__ __forceinline__ uint32_t smem_u32(const void* p) {
    uint32_t a;
    asm("{ .reg .u64 t; cvta.to.shared.u64 t, %1; cvt.u32.u64 %0, t; }"
        : "=r"(a) : "l"(p));
    return a;
}
__device__ __forceinline__ void ldsm4(uint32_t* r, uint32_t addr) {
    asm volatile("ldmatrix.sync.aligned.m8n8.x4.shared.b16 {%0,%1,%2,%3}, [%4];"
        : "=r"(r[0]), "=r"(r[1]), "=r"(r[2]), "=r"(r[3]) : "r"(addr));
}
__device__ __forceinline__ void mma16816(float* d, const uint32_t* a,
                                         uint32_t b0, uint32_t b1) {
    asm volatile("mma.sync.aligned.m16n8k16.row.col.f32.bf16.bf16.f32 "
        "{%0,%1,%2,%3}, {%4,%5,%6,%7}, {%8,%9}, {%0,%1,%2,%3};"
        : "+f"(d[0]), "+f"(d[1]), "+f"(d[2]), "+f"(d[3])
        : "r"(a[0]), "r"(a[1]), "r"(a[2]), "r"(a[3]), "r"(b0), "r"(b1));
}

// K0: split W into bf16 hi/lo, stored directly as mma B-fragments per lane
__global__ __launch_bounds__(256) void wsplit_kernel(const float* __restrict__ W) {
    const int idx  = blockIdx.x * 256 + threadIdx.x;  // 0..8191
    const int lane = idx & 31;
    const int p    = (idx >> 5) & 3;
    const int ks   = (idx >> 7) & 7;
    const int hl   = (idx >> 10) & 1;
    const int wf   = (idx >> 11) & 1;
    const int ft   = (idx >> 12) & 1;
    const int F0 = ft * 128 + wf * 64 + p * 16 + (lane >> 2);
    const int k0 = ks * 16 + (lane & 3) * 2;

    auto elem = [&](int k, int f) -> __nv_bfloat16 {
        float v = W[k * F_OUT + f];
        __nv_bfloat16 h = __float2bfloat16(v);
        if (!hl) return h;
        return __float2bfloat16(v - __bfloat162float(h));
    };
    auto pk = [&](int k, int f) -> uint32_t {
        __nv_bfloat162 t; t.x = elem(k, f); t.y = elem(k + 1, f);
        return *(uint32_t*)&t;
    };
    uint4 r;
    r.x = pk(k0,     F0);
    r.y = pk(k0 + 8, F0);
    r.z = pk(k0,     F0 + 8);
    r.w = pk(k0 + 8, F0 + 8);
    g_Bfrag[idx] = r;
}

// K1: Gram partials G_t = Xs_tile^T Xs_tile (bf16x3) + colsum partials.
// 128 CTAs x 84 rows (exactly 4 shift-groups; pad m to 96 with zeros).
__global__ __launch_bounds__(256, 2) void gram_kernel(const float* __restrict__ x) {
    extern __shared__ char smem[];
    const uint32_t sb = smem_u32(smem);
    const int tid = threadIdx.x;
    const int bid = blockIdx.x;

    // zero-pad m = 84..95 (both tiles)
    for (int i = tid; i < 1536; i += 256) {
        const int c = i / 12, mm = 84 + i % 12;
        const uint32_t off = (uint32_t)(c * GSTR + mm) * 2;
        *(__nv_bfloat16*)(smem + GSM_HI + off) = __float2bfloat16(0.f);
        *(__nv_bfloat16*)(smem + GSM_LO + off) = __float2bfloat16(0.f);
    }
    // gather 84 rows coalesced, shift applied on transposed store [c][m]
    {
        const float* xb = x + (size_t)bid * GBM * C_IN;
        #pragma unroll
        for (int it = 0; it < 11; ++it) {
            const int idx = it * 256 + tid;      // 84*32 = 2688 float4 chunks
            if (idx < 2688) {
                const int rl = idx >> 5;
                const int c4 = (idx & 31) * 4;
                float4 v = *(const float4*)&xb[rl * C_IN + c4];
                const int g   = rl / N_SP;
                const int inn = rl - g * N_SP;
                const float vv[4] = { v.x, v.y, v.z, v.w };
                #pragma unroll
                for (int e = 0; e < 4; ++e) {
                    const int c = c4 + e;
                    int on = inn + c % N_SP;
                    if (on >= N_SP) on -= N_SP;
                    const int lm = g * N_SP + on;
                    float val = vv[e];
                    __nv_bfloat16 h = __float2bfloat16(val);
                    __nv_bfloat16 l = __float2bfloat16(val - __bfloat162float(h));
                    const uint32_t off = (uint32_t)(c * GSTR + lm) * 2;
                    *(__nv_bfloat16*)(smem + GSM_HI + off) = h;
                    *(__nv_bfloat16*)(smem + GSM_LO + off) = l;
                }
            }
        }
    }
    __syncthreads();

    // mainloop: 8 warps, each 64c x 32c' of the 128x128 Gram
    const int lane = tid & 31, wid = tid >> 5;
    const int wc = wid & 1, wq = wid >> 1;
    const int j = lane & 7, g = lane >> 3;

    uint32_t aAd[4], bAd[2];
    #pragma unroll
    for (int t = 0; t < 4; ++t)
        aAd[t] = sb + (uint32_t)((wc * 64 + t * 16 + j + ((g & 1) << 3)) * GSTR
                                 + (g >> 1) * 8) * 2;
    #pragma unroll
    for (int tt = 0; tt < 2; ++tt)
        bAd[tt] = sb + (uint32_t)((wq * 32 + tt * 16 + j + ((g >> 1) << 3)) * GSTR
                                  + (g & 1) * 8) * 2;

    float acc[4][4][4];
    #pragma unroll
    for (int t = 0; t < 4; ++t)
        #pragma unroll
        for (int n = 0; n < 4; ++n)
            #pragma unroll
            for (int e = 0; e < 4; ++e) acc[t][n][e] = 0.f;

    #pragma unroll
    for (int ks = 0; ks < 6; ++ks) {
        const uint32_t kb = ks * 32;         // 16 m * 2B
        uint32_t aH[4][4], aL[4][4], bH[2][4], bL[2][4];
        #pragma unroll
        for (int t = 0; t < 4; ++t) {
            ldsm4(aH[t], aAd[t] + kb);
            ldsm4(aL[t], aAd[t] + (uint32_t)GSM_LO + kb);
        }
        #pragma unroll
        for (int tt = 0; tt < 2; ++tt) {
            ldsm4(bH[tt], bAd[tt] + kb);
            ldsm4(bL[tt], bAd[tt] + (uint32_t)GSM_LO + kb);
        }
        #pragma unroll
        for (int t = 0; t < 4; ++t)
            #pragma unroll
            for (int tt = 0; tt < 2; ++tt)
                #pragma unroll
                for (int u = 0; u < 2; ++u) {
                    const int n = tt * 2 + u;
                    mma16816(acc[t][n], aH[t], bH[tt][2*u], bH[tt][2*u+1]); // hh
                    mma16816(acc[t][n], aH[t], bL[tt][2*u], bL[tt][2*u+1]); // hl
                    mma16816(acc[t][n], aL[t], bH[tt][2*u], bH[tt][2*u+1]); // lh
                }
    }

    // store partial Gram
    float* P = g_gramP + (size_t)bid * 16384;
    const int c0  = wc * 64 + (lane >> 2);
    const int cp0 = wq * 32 + (lane & 3) * 2;
    #pragma unroll
    for (int t = 0; t < 4; ++t)
        #pragma unroll
        for (int n = 0; n < 4; ++n) {
            const int c  = c0 + t * 16;
            const int cp = cp0 + (n >> 1) * 16 + (n & 1) * 8;
            float* d = acc[t][n];
            *(float2*)&P[c * 128 + cp]       = make_float2(d[0], d[1]);
            *(float2*)&P[(c + 8) * 128 + cp] = make_float2(d[2], d[3]);
        }

    // colsum partial (hi+lo from smem; permutation => equals colsum of x tile)
    if (tid < 128) {
        const int c = tid;
        float s = 0.f;
        #pragma unroll 4
        for (int m = 0; m < GBM; ++m) {
            const uint32_t off = (uint32_t)(c * GSTR + m) * 2;
            s += __bfloat162float(*(__nv_bfloat16*)(smem + GSM_HI + off))
               + __bfloat162float(*(__nv_bfloat16*)(smem + GSM_LO + off));
        }
        g_colP[bid * 128 + c] = s;
    }
}

// K2: reduce gram + colsum partials (deterministic fixed order)
__global__ __launch_bounds__(256) void reduce_kernel() {
    const int idx = blockIdx.x * 256 + threadIdx.x;
    if (idx < 16384) {
        const float* p = g_gramP + idx;
        float s = 0.f;
        #pragma unroll 8
        for (int t = 0; t < GT; ++t) s += p[(size_t)t * 16384];
        g_G[idx] = s;
    } else if (idx < 16512) {
        const int c = idx - 16384;
        float s = 0.f;
        #pragma unroll 8
        for (int t = 0; t < GT; ++t) s += g_colP[t * 128 + c];
        g_s[c] = s;
    }
}

// K3: per-f stats from Gram: q_f = W_f^T G W_f, mean_f = s.W_f / M
__global__ __launch_bounds__(256) void stats_kernel(const float* __restrict__ W,
                                                    const float* __restrict__ gamma,
                                                    const float* __restrict__ beta) {
    __shared__ float Wcol[8][132];
    const int tid = threadIdx.x, wid = tid >> 5, lane = tid & 31;
    const int f = blockIdx.x * 8 + wid;     // 32 blocks x 8 warps = 256 f
    #pragma unroll
    for (int k = 0; k < 4; ++k)
        Wcol[wid][lane + 32 * k] = W[(lane + 32 * k) * F_OUT + f];
    __syncwarp();

    float q = 0.f, mp = 0.f;
    #pragma unroll
    for (int k = 0; k < 4; ++k) {
        const int c = lane + 32 * k;
        const float wc = Wcol[wid][c];
        float u = 0.f;
        const float4* Gr = (const float4*)&g_G[c * 128];
        #pragma unroll 8
        for (int i = 0; i < 32; ++i) {
            float4 gv = Gr[i];
            u += gv.x * Wcol[wid][4*i]   + gv.y * Wcol[wid][4*i+1]
               + gv.z * Wcol[wid][4*i+2] + gv.w * Wcol[wid][4*i+3];
        }
        q  += wc * u;
        mp += wc * g_s[c];
    }
    #pragma unroll
    for (int o = 16; o > 0; o >>= 1) {
        q  += __shfl_xor_sync(0xffffffffu, q, o);
        mp += __shfl_xor_sync(0xffffffffu, mp, o);
    }
    if (lane == 0) {
        const float inv = 1.0f / (float)M_TOTAL;
        float mean = mp * inv;
        float var  = q * inv - mean * mean;
        float sc   = gamma[f] * rsqrtf(var + 1e-3f);
        g_scale[f] = sc;
        g_shift[f] = beta[f] - mean * sc;
    }
}

// K4: fused shift+GEMM + normalize + relu -> out directly (no y round-trip)
__global__ __launch_bounds__(256, 3) void gemm_kernel(const float* __restrict__ x,
                                                      float* __restrict__ out) {
    extern __shared__ char smem[];
    const uint32_t sb = smem_u32(smem);
    const int tid   = threadIdx.x;
    const int ftile = blockIdx.x;            // 0..1
    const int mtile = blockIdx.y;            // 0..167
    const int m0    = mtile * BM;

    // ---- A: coalesced float4 load of 4 whole bt-groups, shift on store ----
    {
        const int gs = m0 / N_SP;
        const float* xb = x + gs * N_SP * C_IN;
        #pragma unroll
        for (int it = 0; it < 11; ++it) {
            const int idx = it * 256 + tid;  // 84 rows * 32 float4 = 2688
            if (idx < 2688) {
                const int rl = idx >> 5;
                const int c4 = (idx & 31) * 4;
                float4 v = *(const float4*)&xb[rl * C_IN + c4];
                const int g   = rl / N_SP;
                const int inn = rl - g * N_SP;
                const int bm  = (gs + g) * N_SP - m0;
                const float vv[4] = { v.x, v.y, v.z, v.w };
                #pragma unroll
                for (int e = 0; e < 4; ++e) {
                    const int c = c4 + e;
                    int on = inn + c % N_SP;
                    if (on >= N_SP) on -= N_SP;
                    const int lm = bm + on;
                    if (lm >= 0 && lm < 64) {
                        float val = vv[e];
                        __nv_bfloat16 h = __float2bfloat16(val);
                        __nv_bfloat16 l = __float2bfloat16(val - __bfloat162float(h));
                        *(__nv_bfloat16*)(smem + SM_AHI + lm * TSTR + c * 2) = h;
                        *(__nv_bfloat16*)(smem + SM_ALO + lm * TSTR + c * 2) = l;
                    }
                }
            }
        }
    }
    __syncthreads();

    // ---- mainloop: A via ldmatrix, B via direct global fragment loads ----
    const int lane = tid & 31, wid = tid >> 5;
    const int warp_m = wid & 3, warp_f = wid >> 2;
    const int j = lane & 7, g = lane >> 3;
    const uint32_t aoff = (uint32_t)((warp_m * 16 + j + ((g & 1) << 3)) * TSTR
                                     + ((g >> 1) * 8) * 2);
    const uint32_t aHI = sb + SM_AHI + aoff, aLO = sb + SM_ALO + aoff;
    const uint4* BH = g_Bfrag + (ftile * 2 + warp_f) * 2048 + lane;
    const uint4* BL = BH + 1024;

    float acc[8][4];
    #pragma unroll
    for (int a = 0; a < 8; ++a)
        #pragma unroll
        for (int e = 0; e < 4; ++e) acc[a][e] = 0.f;

    #pragma unroll
    for (int ks = 0; ks < 8; ++ks) {
        uint32_t ah[4], al[4];
        ldsm4(ah, aHI + ks * 32);
        ldsm4(al, aLO + ks * 32);
        #pragma unroll
        for (int p = 0; p < 4; ++p) {
            const uint4 bh = __ldg(BH + (ks * 4 + p) * 32);
            const uint4 bl = __ldg(BL + (ks * 4 + p) * 32);
            mma16816(acc[p * 2],     ah, bh.x, bh.y);   // hh
            mma16816(acc[p * 2 + 1], ah, bh.z, bh.w);
            mma16816(acc[p * 2],     ah, bl.x, bl.y);   // hl
            mma16816(acc[p * 2 + 1], ah, bl.z, bl.w);
            mma16816(acc[p * 2],     al, bh.x, bh.y);   // lh
            mma16816(acc[p * 2 + 1], al, bh.z, bh.w);
        }
    }

    // ---- epilogue: scale/shift + relu straight from accumulators ----
    const int r0 = m0 + warp_m * 16 + (lane >> 2);
    #pragma unroll
    for (int p = 0; p < 4; ++p)
        #pragma unroll
        for (int u = 0; u < 2; ++u) {
            const int col = ftile * 128 + warp_f * 64 + p * 16 + u * 8 + (lane & 3) * 2;
            float2 sc = *(const float2*)&g_scale[col];
            float2 sh = *(const float2*)&g_shift[col];
            float* d = acc[p * 2 + u];
            float2 o0, o1;
            o0.x = fmaxf(fmaf(d[0], sc.x, sh.x), 0.f);
            o0.y = fmaxf(fmaf(d[1], sc.y, sh.y), 0.f);
            o1.x = fmaxf(fmaf(d[2], sc.x, sh.x), 0.f);
            o1.y = fmaxf(fmaf(d[3], sc.y, sh.y), 0.f);
            *(float2*)&out[(size_t)r0 * F_OUT + col]       = o0;
            *(float2*)&out[(size_t)(r0 + 8) * F_OUT + col] = o1;
        }
}

extern "C" void kernel_launch(void* const* d_in, const int* in_sizes, int n_in,
                              void* d_out, int out_size) {
    const float* x     = (const float*)d_in[0];
    const float* W     = (const float*)d_in[1];
    // d_in[2] = conv bias b: cancels exactly under BatchNorm -> unused
    const float* gamma = (const float*)d_in[3];
    const float* beta  = (const float*)d_in[4];

    cudaFuncSetAttribute(gram_kernel, cudaFuncAttributeMaxDynamicSharedMemorySize, GSM_TOT);
    cudaFuncSetAttribute(gemm_kernel, cudaFuncAttributeMaxDynamicSharedMemorySize, SM_TOT);

    wsplit_kernel<<<32, 256>>>(W);
    gram_kernel<<<GT, 256, GSM_TOT>>>(x);
    reduce_kernel<<<65, 256>>>();
    stats_kernel<<<32, 256>>>(W, gamma, beta);
    gemm_kernel<<<dim3(2, MT), 256, SM_TOT>>>(x, (float*)d_out);
}

// round 11
// speedup vs baseline: 1.4354x; 1.4354x over previous
#include <cuda_runtime.h>
#include <cuda_bf16.h>
#include <cstdint>

// Shapes
#define M_TOTAL 10752          // B*T*N = 8*64*21
#define C_IN    128
#define F_OUT   256
#define N_SP    21
#define BM      64
#define MT      (M_TOTAL / BM) // 168 m-tiles

// --- gemm smem: A hi/lo (bf16, padded rows for conflict-free ldmatrix) ---
#define TSTR    272
#define SM_AHI  0
#define SM_ALO  (SM_AHI + 64 * TSTR)      // 17408
#define SM_TOT  (SM_ALO + 64 * TSTR)      // 34816

// --- gram smem: transposed Xs tile [c][m], 96 m padded, 208B rows ---
#define GSTR    104                        // bf16 elems/row = 208B (13*16B)
#define GSM_HI  0
#define GSM_LO  (128 * GSTR * 2)           // 26624
#define GSM_TOT (2 * 128 * GSTR * 2)       // 53248
#define GBM     84                         // 4 shift-groups per gram tile
#define GT      (M_TOTAL / GBM)            // 128 gram tiles

// Scratch (allocation-free device globals)
__device__ float g_gramP[GT * 128 * 128];    // 8 MB gram partials
__device__ float g_colP [GT * 128];          // colsum partials
__device__ float g_G[128 * 128];             // reduced Gram
__device__ float g_s[128];                   // reduced colsum
__device__ float g_scale[F_OUT];
__device__ float g_shift[F_OUT];
// W as per-lane mma B-fragments: [ft][wf][hl][ks][p][lane]
__device__ uint4 g_Bfrag[8192];              // 128 KB, L1-resident

__device__ __forceinline__ uint32_t smem_u32(const void* p) {
    uint32_t a;
    asm("{ .reg .u64 t; cvta.to.shared.u64 t, %1; cvt.u32.u64 %0, t; }"
        : "=r"(a) : "l"(p));
    return a;
}
__device__ __forceinline__ void ldsm4(uint32_t* r, uint32_t addr) {
    asm volatile("ldmatrix.sync.aligned.m8n8.x4.shared.b16 {%0,%1,%2,%3}, [%4];"
        : "=r"(r[0]), "=r"(r[1]), "=r"(r[2]), "=r"(r[3]) : "r"(addr));
}
__device__ __forceinline__ void mma16816(float* d, const uint32_t* a,
                                         uint32_t b0, uint32_t b1) {
    asm volatile("mma.sync.aligned.m16n8k16.row.col.f32.bf16.bf16.f32 "
        "{%0,%1,%2,%3}, {%4,%5,%6,%7}, {%8,%9}, {%0,%1,%2,%3};"
        : "+f"(d[0]), "+f"(d[1]), "+f"(d[2]), "+f"(d[3])
        : "r"(a[0]), "r"(a[1]), "r"(a[2]), "r"(a[3]), "r"(b0), "r"(b1));
}

// K0: split W into bf16 hi/lo, stored directly as mma B-fragments per lane
__global__ __launch_bounds__(256) void wsplit_kernel(const float* __restrict__ W) {
    const int idx  = blockIdx.x * 256 + threadIdx.x;  // 0..8191
    const int lane = idx & 31;
    const int p    = (idx >> 5) & 3;
    const int ks   = (idx >> 7) & 7;
    const int hl   = (idx >> 10) & 1;
    const int wf   = (idx >> 11) & 1;
    const int ft   = (idx >> 12) & 1;
    const int F0 = ft * 128 + wf * 64 + p * 16 + (lane >> 2);
    const int k0 = ks * 16 + (lane & 3) * 2;

    auto elem = [&](int k, int f) -> __nv_bfloat16 {
        float v = W[k * F_OUT + f];
        __nv_bfloat16 h = __float2bfloat16(v);
        if (!hl) return h;
        return __float2bfloat16(v - __bfloat162float(h));
    };
    auto pk = [&](int k, int f) -> uint32_t {
        __nv_bfloat162 t; t.x = elem(k, f); t.y = elem(k + 1, f);
        return *(uint32_t*)&t;
    };
    uint4 r;
    r.x = pk(k0,     F0);
    r.y = pk(k0 + 8, F0);
    r.z = pk(k0,     F0 + 8);
    r.w = pk(k0 + 8, F0 + 8);
    g_Bfrag[idx] = r;
}

// K1: Gram partials G_t = Xs_tile^T Xs_tile (bf16x3) + colsum partials.
// 128 CTAs x 84 rows (exactly 4 shift-groups; pad m to 96 with zeros).
__global__ __launch_bounds__(256, 2) void gram_kernel(const float* __restrict__ x) {
    extern __shared__ char smem[];
    const uint32_t sb = smem_u32(smem);
    const int tid = threadIdx.x;
    const int bid = blockIdx.x;

    // zero-pad m = 84..95 (both tiles)
    for (int i = tid; i < 1536; i += 256) {
        const int c = i / 12, mm = 84 + i % 12;
        const uint32_t off = (uint32_t)(c * GSTR + mm) * 2;
        *(__nv_bfloat16*)(smem + GSM_HI + off) = __float2bfloat16(0.f);
        *(__nv_bfloat16*)(smem + GSM_LO + off) = __float2bfloat16(0.f);
    }
    // gather 84 rows coalesced, shift applied on transposed store [c][m]
    {
        const float* xb = x + (size_t)bid * GBM * C_IN;
        #pragma unroll
        for (int it = 0; it < 11; ++it) {
            const int idx = it * 256 + tid;      // 84*32 = 2688 float4 chunks
            if (idx < 2688) {
                const int rl = idx >> 5;
                const int c4 = (idx & 31) * 4;
                float4 v = *(const float4*)&xb[rl * C_IN + c4];
                const int g   = rl / N_SP;
                const int inn = rl - g * N_SP;
                const float vv[4] = { v.x, v.y, v.z, v.w };
                #pragma unroll
                for (int e = 0; e < 4; ++e) {
                    const int c = c4 + e;
                    int on = inn + c % N_SP;
                    if (on >= N_SP) on -= N_SP;
                    const int lm = g * N_SP + on;
                    float val = vv[e];
                    __nv_bfloat16 h = __float2bfloat16(val);
                    __nv_bfloat16 l = __float2bfloat16(val - __bfloat162float(h));
                    const uint32_t off = (uint32_t)(c * GSTR + lm) * 2;
                    *(__nv_bfloat16*)(smem + GSM_HI + off) = h;
                    *(__nv_bfloat16*)(smem + GSM_LO + off) = l;
                }
            }
        }
    }
    __syncthreads();

    // mainloop: 8 warps, each 64c x 32c' of the 128x128 Gram
    const int lane = tid & 31, wid = tid >> 5;
    const int wc = wid & 1, wq = wid >> 1;
    const int j = lane & 7, g = lane >> 3;

    uint32_t aAd[4], bAd[2];
    #pragma unroll
    for (int t = 0; t < 4; ++t)
        aAd[t] = sb + (uint32_t)((wc * 64 + t * 16 + j + ((g & 1) << 3)) * GSTR
                                 + (g >> 1) * 8) * 2;
    #pragma unroll
    for (int tt = 0; tt < 2; ++tt)
        bAd[tt] = sb + (uint32_t)((wq * 32 + tt * 16 + j + ((g >> 1) << 3)) * GSTR
                                  + (g & 1) * 8) * 2;

    float acc[4][4][4];
    #pragma unroll
    for (int t = 0; t < 4; ++t)
        #pragma unroll
        for (int n = 0; n < 4; ++n)
            #pragma unroll
            for (int e = 0; e < 4; ++e) acc[t][n][e] = 0.f;

    #pragma unroll
    for (int ks = 0; ks < 6; ++ks) {
        const uint32_t kb = ks * 32;         // 16 m * 2B
        uint32_t aH[4][4], aL[4][4], bH[2][4], bL[2][4];
        #pragma unroll
        for (int t = 0; t < 4; ++t) {
            ldsm4(aH[t], aAd[t] + kb);
            ldsm4(aL[t], aAd[t] + (uint32_t)GSM_LO + kb);
        }
        #pragma unroll
        for (int tt = 0; tt < 2; ++tt) {
            ldsm4(bH[tt], bAd[tt] + kb);
            ldsm4(bL[tt], bAd[tt] + (uint32_t)GSM_LO + kb);
        }
        #pragma unroll
        for (int t = 0; t < 4; ++t)
            #pragma unroll
            for (int tt = 0; tt < 2; ++tt)
                #pragma unroll
                for (int u = 0; u < 2; ++u) {
                    const int n = tt * 2 + u;
                    mma16816(acc[t][n], aH[t], bH[tt][2*u], bH[tt][2*u+1]); // hh
                    mma16816(acc[t][n], aH[t], bL[tt][2*u], bL[tt][2*u+1]); // hl
                    mma16816(acc[t][n], aL[t], bH[tt][2*u], bH[tt][2*u+1]); // lh
                }
    }

    // store partial Gram
    float* P = g_gramP + (size_t)bid * 16384;
    const int c0  = wc * 64 + (lane >> 2);
    const int cp0 = wq * 32 + (lane & 3) * 2;
    #pragma unroll
    for (int t = 0; t < 4; ++t)
        #pragma unroll
        for (int n = 0; n < 4; ++n) {
            const int c  = c0 + t * 16;
            const int cp = cp0 + (n >> 1) * 16 + (n & 1) * 8;
            float* d = acc[t][n];
            *(float2*)&P[c * 128 + cp]       = make_float2(d[0], d[1]);
            *(float2*)&P[(c + 8) * 128 + cp] = make_float2(d[2], d[3]);
        }

    // colsum partial (hi+lo from smem; permutation => equals colsum of x tile)
    if (tid < 128) {
        const int c = tid;
        float s = 0.f;
        #pragma unroll 4
        for (int m = 0; m < GBM; ++m) {
            const uint32_t off = (uint32_t)(c * GSTR + m) * 2;
            s += __bfloat162float(*(__nv_bfloat16*)(smem + GSM_HI + off))
               + __bfloat162float(*(__nv_bfloat16*)(smem + GSM_LO + off));
        }
        g_colP[bid * 128 + c] = s;
    }
}

// K2: reduce gram + colsum partials. 129 blocks x 256 threads.
// Block b<128: 128 G-elements, each summed by 2 threads (64 tiles each) + smem
// combine -> halves the exposed-latency chain vs single-thread 128-tile sums.
__global__ __launch_bounds__(256) void reduce_kernel() {
    __shared__ float sbuf[256];
    const int tid  = threadIdx.x;
    const int b    = blockIdx.x;
    const int el   = tid & 127;
    const int half = tid >> 7;               // 0..1 -> tiles [0,64) / [64,128)
    if (b < 128) {
        const int e = b * 128 + el;
        const float* p = g_gramP + (size_t)(half * 64) * 16384 + e;
        float s = 0.f;
        #pragma unroll 16
        for (int t = 0; t < 64; ++t) s += p[(size_t)t * 16384];
        sbuf[tid] = s;
        __syncthreads();
        if (half == 0) g_G[e] = sbuf[el] + sbuf[128 + el];
    } else {
        const float* p = g_colP + half * 64 * 128 + el;
        float s = 0.f;
        #pragma unroll 16
        for (int t = 0; t < 64; ++t) s += p[t * 128];
        sbuf[tid] = s;
        __syncthreads();
        if (half == 0) g_s[el] = sbuf[el] + sbuf[128 + el];
    }
}

// K3: per-f stats from Gram: q_f = W_f^T G W_f, mean_f = s.W_f / M.
// 256 blocks (one per f) x 256 threads; thread owns 64 contiguous G elements
// (c = tid>>1 is constant per thread), fully coalesced, MLP=16.
__global__ __launch_bounds__(256) void stats_kernel(const float* __restrict__ W,
                                                    const float* __restrict__ gamma,
                                                    const float* __restrict__ beta) {
    __shared__ float Wf[128];
    __shared__ float red[256];
    __shared__ float mred;
    const int tid = threadIdx.x;
    const int f   = blockIdx.x;
    if (tid < 128) Wf[tid] = W[tid * F_OUT + f];
    __syncthreads();

    const int c  = tid >> 1;
    const int i0 = (tid & 1) * 64;
    const float4* Gp = (const float4*)(g_G + tid * 64);
    float u = 0.f;
    #pragma unroll
    for (int l = 0; l < 16; ++l) {
        float4 gv = Gp[l];
        const int i = i0 + l * 4;
        u += gv.x * Wf[i] + gv.y * Wf[i + 1] + gv.z * Wf[i + 2] + gv.w * Wf[i + 3];
    }
    red[tid] = Wf[c] * u;
    __syncthreads();
    #pragma unroll
    for (int o = 128; o >= 32; o >>= 1) {
        if (tid < o) red[tid] += red[tid + o];
        __syncthreads();
    }
    if (tid < 32) {
        float q = red[tid];
        #pragma unroll
        for (int o = 16; o > 0; o >>= 1) q += __shfl_xor_sync(0xffffffffu, q, o);
        // mean partial on warp 0
        float mp = 0.f;
        #pragma unroll
        for (int k = 0; k < 4; ++k) {
            const int cc = tid + 32 * k;
            mp += Wf[cc] * g_s[cc];
        }
        #pragma unroll
        for (int o = 16; o > 0; o >>= 1) mp += __shfl_xor_sync(0xffffffffu, mp, o);
        if (tid == 0) {
            const float inv = 1.0f / (float)M_TOTAL;
            float mean = mp * inv;
            float var  = q * inv - mean * mean;
            float sc   = gamma[f] * rsqrtf(var + 1e-3f);
            g_scale[f] = sc;
            g_shift[f] = beta[f] - mean * sc;
        }
    }
}

// K4: fused shift+GEMM + normalize + relu -> out directly (no y round-trip)
__global__ __launch_bounds__(256, 3) void gemm_kernel(const float* __restrict__ x,
                                                      float* __restrict__ out) {
    extern __shared__ char smem[];
    const uint32_t sb = smem_u32(smem);
    const int tid   = threadIdx.x;
    const int ftile = blockIdx.x;            // 0..1
    const int mtile = blockIdx.y;            // 0..167
    const int m0    = mtile * BM;

    // ---- A: coalesced float4 load of 4 whole bt-groups, shift on store ----
    {
        const int gs = m0 / N_SP;
        const float* xb = x + gs * N_SP * C_IN;
        #pragma unroll
        for (int it = 0; it < 11; ++it) {
            const int idx = it * 256 + tid;  // 84 rows * 32 float4 = 2688
            if (idx < 2688) {
                const int rl = idx >> 5;
                const int c4 = (idx & 31) * 4;
                float4 v = *(const float4*)&xb[rl * C_IN + c4];
                const int g   = rl / N_SP;
                const int inn = rl - g * N_SP;
                const int bm  = (gs + g) * N_SP - m0;
                const float vv[4] = { v.x, v.y, v.z, v.w };
                #pragma unroll
                for (int e = 0; e < 4; ++e) {
                    const int c = c4 + e;
                    int on = inn + c % N_SP;
                    if (on >= N_SP) on -= N_SP;
                    const int lm = bm + on;
                    if (lm >= 0 && lm < 64) {
                        float val = vv[e];
                        __nv_bfloat16 h = __float2bfloat16(val);
                        __nv_bfloat16 l = __float2bfloat16(val - __bfloat162float(h));
                        *(__nv_bfloat16*)(smem + SM_AHI + lm * TSTR + c * 2) = h;
                        *(__nv_bfloat16*)(smem + SM_ALO + lm * TSTR + c * 2) = l;
                    }
                }
            }
        }
    }
    __syncthreads();

    // ---- mainloop: A via ldmatrix, B via direct global fragment loads ----
    const int lane = tid & 31, wid = tid >> 5;
    const int warp_m = wid & 3, warp_f = wid >> 2;
    const int j = lane & 7, g = lane >> 3;
    const uint32_t aoff = (uint32_t)((warp_m * 16 + j + ((g & 1) << 3)) * TSTR
                                     + ((g >> 1) * 8) * 2);
    const uint32_t aHI = sb + SM_AHI + aoff, aLO = sb + SM_ALO + aoff;
    const uint4* BH = g_Bfrag + (ftile * 2 + warp_f) * 2048 + lane;
    const uint4* BL = BH + 1024;

    float acc[8][4];
    #pragma unroll
    for (int a = 0; a < 8; ++a)
        #pragma unroll
        for (int e = 0; e < 4; ++e) acc[a][e] = 0.f;

    #pragma unroll
    for (int ks = 0; ks < 8; ++ks) {
        uint32_t ah[4], al[4];
        ldsm4(ah, aHI + ks * 32);
        ldsm4(al, aLO + ks * 32);
        #pragma unroll
        for (int p = 0; p < 4; ++p) {
            const uint4 bh = __ldg(BH + (ks * 4 + p) * 32);
            const uint4 bl = __ldg(BL + (ks * 4 + p) * 32);
            mma16816(acc[p * 2],     ah, bh.x, bh.y);   // hh
            mma16816(acc[p * 2 + 1], ah, bh.z, bh.w);
            mma16816(acc[p * 2],     ah, bl.x, bl.y);   // hl
            mma16816(acc[p * 2 + 1], ah, bl.z, bl.w);
            mma16816(acc[p * 2],     al, bh.x, bh.y);   // lh
            mma16816(acc[p * 2 + 1], al, bh.z, bh.w);
        }
    }

    // ---- epilogue: scale/shift + relu straight from accumulators ----
    const int r0 = m0 + warp_m * 16 + (lane >> 2);
    #pragma unroll
    for (int p = 0; p < 4; ++p)
        #pragma unroll
        for (int u = 0; u < 2; ++u) {
            const int col = ftile * 128 + warp_f * 64 + p * 16 + u * 8 + (lane & 3) * 2;
            float2 sc = *(const float2*)&g_scale[col];
            float2 sh = *(const float2*)&g_shift[col];
            float* d = acc[p * 2 + u];
            float2 o0, o1;
            o0.x = fmaxf(fmaf(d[0], sc.x, sh.x), 0.f);
            o0.y = fmaxf(fmaf(d[1], sc.y, sh.y), 0.f);
            o1.x = fmaxf(fmaf(d[2], sc.x, sh.x), 0.f);
            o1.y = fmaxf(fmaf(d[3], sc.y, sh.y), 0.f);
            *(float2*)&out[(size_t)r0 * F_OUT + col]       = o0;
            *(float2*)&out[(size_t)(r0 + 8) * F_OUT + col] = o1;
        }
}

extern "C" void kernel_launch(void* const* d_in, const int* in_sizes, int n_in,
                              void* d_out, int out_size) {
    const float* x     = (const float*)d_in[0];
    const float* W     = (const float*)d_in[1];
    // d_in[2] = conv bias b: cancels exactly under BatchNorm -> unused
    const float* gamma = (const float*)d_in[3];
    const float* beta  = (const float*)d_in[4];

    cudaFuncSetAttribute(gram_kernel, cudaFuncAttributeMaxDynamicSharedMemorySize, GSM_TOT);
    cudaFuncSetAttribute(gemm_kernel, cudaFuncAttributeMaxDynamicSharedMemorySize, SM_TOT);

    wsplit_kernel<<<32, 256>>>(W);
    gram_kernel<<<GT, 256, GSM_TOT>>>(x);
    reduce_kernel<<<129, 256>>>();
    stats_kernel<<<256, 256>>>(W, gamma, beta);
    gemm_kernel<<<dim3(2, MT), 256, SM_TOT>>>(x, (float*)d_out);
}

// round 12
// speedup vs baseline: 1.8368x; 1.2797x over previous
#include <cuda_runtime.h>
#include <cuda_bf16.h>
#include <cstdint>

// Shapes
#define M_TOTAL 10752          // B*T*N = 8*64*21
#define C_IN    128
#define F_OUT   256
#define N_SP    21
#define BM      64
#define MT      (M_TOTAL / BM) // 168 m-tiles
#define NCTA    (2 * MT)       // 336 CTAs, single resident wave at 3/SM

// SMEM: A hi/lo (bf16, padded rows for conflict-free ldmatrix); Y reuses A.
#define TSTR    272
#define SM_AHI  0
#define SM_ALO  (SM_AHI + 64 * TSTR)      // 17408
#define SM_PS   (SM_ALO + 64 * TSTR)      // 34816
#define SM_PQ   (SM_PS + 1024)
#define SM_TOT  (SM_PQ + 1024)            // 36864 -> 3 CTAs/SM guaranteed
#define YS      132                        // y staging stride (floats)

// Scratch (allocation-free device globals)
__device__ float g_psum[MT * F_OUT];
__device__ float g_psq [MT * F_OUT];
__device__ float g_scale[F_OUT];
__device__ float g_shift[F_OUT];
__device__ unsigned int g_ctr;
__device__ volatile unsigned int g_flag;
// W as per-lane mma B-fragments: [ft][wf][hl][ks][p][lane]
__device__ uint4 g_Bfrag[8192];              // 128 KB, L1-resident

__device__ __forceinline__ uint32_t smem_u32(const void* p) {
    uint32_t a;
    asm("{ .reg .u64 t; cvta.to.shared.u64 t, %1; cvt.u32.u64 %0, t; }"
        : "=r"(a) : "l"(p));
    return a;
}
__device__ __forceinline__ void ldsm4(uint32_t* r, uint32_t addr) {
    asm volatile("ldmatrix.sync.aligned.m8n8.x4.shared.b16 {%0,%1,%2,%3}, [%4];"
        : "=r"(r[0]), "=r"(r[1]), "=r"(r[2]), "=r"(r[3]) : "r"(addr));
}
__device__ __forceinline__ void mma16816(float* d, const uint32_t* a,
                                         uint32_t b0, uint32_t b1) {
    asm volatile("mma.sync.aligned.m16n8k16.row.col.f32.bf16.bf16.f32 "
        "{%0,%1,%2,%3}, {%4,%5,%6,%7}, {%8,%9}, {%0,%1,%2,%3};"
        : "+f"(d[0]), "+f"(d[1]), "+f"(d[2]), "+f"(d[3])
        : "r"(a[0]), "r"(a[1]), "r"(a[2]), "r"(a[3]), "r"(b0), "r"(b1));
}

// K0: split W into bf16 hi/lo mma B-fragments; also reset ctr/flag (graph-replay safe)
__global__ __launch_bounds__(256) void wsplit_kernel(const float* __restrict__ W) {
    if (blockIdx.x == 0 && threadIdx.x == 0) { g_ctr = 0; g_flag = 0; }
    const int idx  = blockIdx.x * 256 + threadIdx.x;  // 0..8191
    const int lane = idx & 31;
    const int p    = (idx >> 5) & 3;
    const int ks   = (idx >> 7) & 7;
    const int hl   = (idx >> 10) & 1;
    const int wf   = (idx >> 11) & 1;
    const int ft   = (idx >> 12) & 1;
    const int F0 = ft * 128 + wf * 64 + p * 16 + (lane >> 2);
    const int k0 = ks * 16 + (lane & 3) * 2;

    auto elem = [&](int k, int f) -> __nv_bfloat16 {
        float v = W[k * F_OUT + f];
        __nv_bfloat16 h = __float2bfloat16(v);
        if (!hl) return h;
        return __float2bfloat16(v - __bfloat162float(h));
    };
    auto pk = [&](int k, int f) -> uint32_t {
        __nv_bfloat162 t; t.x = elem(k, f); t.y = elem(k + 1, f);
        return *(uint32_t*)&t;
    };
    uint4 r;
    r.x = pk(k0,     F0);
    r.y = pk(k0 + 8, F0);
    r.z = pk(k0,     F0 + 8);
    r.w = pk(k0 + 8, F0 + 8);
    g_Bfrag[idx] = r;
}

// K1: fully fused shift+GEMM+BN+ReLU. Single co-resident wave (336 <= 444):
// per-CTA partials -> last CTA computes scale/shift -> flag -> all normalize
// from the Y tile still staged in smem.
__global__ __launch_bounds__(256, 3) void fused_kernel(const float* __restrict__ x,
                                                       const float* __restrict__ gamma,
                                                       const float* __restrict__ beta,
                                                       float* __restrict__ out) {
    extern __shared__ char smem[];
    const uint32_t sb = smem_u32(smem);
    const int tid   = threadIdx.x;
    const int ftile = blockIdx.x;            // 0..1
    const int mtile = blockIdx.y;            // 0..167
    const int m0    = mtile * BM;

    // ---- A: coalesced float4 load of 4 whole bt-groups, shift on store ----
    {
        const int gs = m0 / N_SP;
        const float* xb = x + gs * N_SP * C_IN;
        #pragma unroll
        for (int it = 0; it < 11; ++it) {
            const int idx = it * 256 + tid;  // 84 rows * 32 float4 = 2688
            if (idx < 2688) {
                const int rl = idx >> 5;
                const int c4 = (idx & 31) * 4;
                float4 v = *(const float4*)&xb[rl * C_IN + c4];
                const int g   = rl / N_SP;
                const int inn = rl - g * N_SP;
                const int bm  = (gs + g) * N_SP - m0;
                const float vv[4] = { v.x, v.y, v.z, v.w };
                #pragma unroll
                for (int e = 0; e < 4; ++e) {
                    const int c = c4 + e;
                    int on = inn + c % N_SP;
                    if (on >= N_SP) on -= N_SP;
                    const int lm = bm + on;
                    if (lm >= 0 && lm < 64) {
                        float val = vv[e];
                        __nv_bfloat16 h = __float2bfloat16(val);
                        __nv_bfloat16 l = __float2bfloat16(val - __bfloat162float(h));
                        *(__nv_bfloat16*)(smem + SM_AHI + lm * TSTR + c * 2) = h;
                        *(__nv_bfloat16*)(smem + SM_ALO + lm * TSTR + c * 2) = l;
                    }
                }
            }
        }
    }
    __syncthreads();

    // ---- mainloop: A via ldmatrix, B via direct global fragment loads ----
    const int lane = tid & 31, wid = tid >> 5;
    const int warp_m = wid & 3, warp_f = wid >> 2;
    const int j = lane & 7, g = lane >> 3;
    const uint32_t aoff = (uint32_t)((warp_m * 16 + j + ((g & 1) << 3)) * TSTR
                                     + ((g >> 1) * 8) * 2);
    const uint32_t aHI = sb + SM_AHI + aoff, aLO = sb + SM_ALO + aoff;
    const uint4* BH = g_Bfrag + (ftile * 2 + warp_f) * 2048 + lane;
    const uint4* BL = BH + 1024;

    float acc[8][4];
    #pragma unroll
    for (int a = 0; a < 8; ++a)
        #pragma unroll
        for (int e = 0; e < 4; ++e) acc[a][e] = 0.f;

    #pragma unroll
    for (int ks = 0; ks < 8; ++ks) {
        uint32_t ah[4], al[4];
        ldsm4(ah, aHI + ks * 32);
        ldsm4(al, aLO + ks * 32);
        #pragma unroll
        for (int p = 0; p < 4; ++p) {
            const uint4 bh = __ldg(BH + (ks * 4 + p) * 32);
            const uint4 bl = __ldg(BL + (ks * 4 + p) * 32);
            mma16816(acc[p * 2],     ah, bh.x, bh.y);   // hh
            mma16816(acc[p * 2 + 1], ah, bh.z, bh.w);
            mma16816(acc[p * 2],     ah, bl.x, bl.y);   // hl
            mma16816(acc[p * 2 + 1], ah, bl.z, bl.w);
            mma16816(acc[p * 2],     al, bh.x, bh.y);   // lh
            mma16816(acc[p * 2 + 1], al, bh.z, bh.w);
        }
    }
    __syncthreads();                          // A region dead -> reuse as Y

    // ---- stage y tile [64][YS] in smem; per-CTA BN partials -> global ----
    float* Y  = (float*)(smem + SM_AHI);
    float* Ps = (float*)(smem + SM_PS);
    float* Pq = (float*)(smem + SM_PQ);
    {
        const int r0 = warp_m * 16 + (lane >> 2);
        #pragma unroll
        for (int p = 0; p < 4; ++p)
            #pragma unroll
            for (int u = 0; u < 2; ++u) {
                const int col = warp_f * 64 + p * 16 + u * 8 + (lane & 3) * 2;
                float* d = acc[p * 2 + u];
                *(float2*)&Y[r0 * YS + col]       = make_float2(d[0], d[1]);
                *(float2*)&Y[(r0 + 8) * YS + col] = make_float2(d[2], d[3]);
            }
    }
    __syncthreads();
    {
        const int part = tid >> 7, f = tid & 127;   // 2 parts x 32 rows
        float s = 0.f, q = 0.f;
        #pragma unroll 8
        for (int r = 0; r < 32; ++r) {
            float v = Y[(part * 32 + r) * YS + f];
            s += v; q += v * v;
        }
        Ps[part * 128 + f] = s;
        Pq[part * 128 + f] = q;
    }
    __syncthreads();
    if (tid < 128) {
        g_psum[mtile * F_OUT + ftile * 128 + tid] = Ps[tid] + Ps[128 + tid];
        g_psq [mtile * F_OUT + ftile * 128 + tid] = Pq[tid] + Pq[128 + tid];
    }
    __threadfence();
    __syncthreads();

    // ---- arrival; last CTA computes scale/shift and releases the flag ----
    __shared__ unsigned int s_last;
    if (tid == 0) s_last = (atomicAdd(&g_ctr, 1u) == NCTA - 1) ? 1u : 0u;
    __syncthreads();

    if (s_last) {
        const int f = tid;                    // 256 threads, one f each
        float s = 0.f, q = 0.f;
        #pragma unroll 8
        for (int t = 0; t < MT; ++t) {
            s += g_psum[t * F_OUT + f];
            q += g_psq [t * F_OUT + f];
        }
        const float inv = 1.0f / (float)M_TOTAL;
        float mean = s * inv;
        float var  = q * inv - mean * mean;
        float sc   = gamma[f] * rsqrtf(var + 1e-3f);
        g_scale[f] = sc;
        g_shift[f] = beta[f] - mean * sc;
        __threadfence();
        __syncthreads();
        if (tid == 0) g_flag = 1u;
    } else if (tid == 0) {
        while (g_flag == 0u) __nanosleep(64);
    }
    __syncthreads();
    __threadfence();

    // ---- stage this ftile's scale/shift, then normalize Y -> out ----
    if (tid < 128) {
        Ps[tid] = g_scale[ftile * 128 + tid];
        Pq[tid] = g_shift[ftile * 128 + tid];
    }
    __syncthreads();
    #pragma unroll
    for (int i = 0; i < 8; ++i) {
        const int id = i * 256 + tid;
        const int r = id >> 5, c4 = (id & 31) * 4;
        float4 y = *(const float4*)&Y[r * YS + c4];
        float4 sc = *(const float4*)&Ps[c4];
        float4 sh = *(const float4*)&Pq[c4];
        float4 o;
        o.x = fmaxf(fmaf(y.x, sc.x, sh.x), 0.f);
        o.y = fmaxf(fmaf(y.y, sc.y, sh.y), 0.f);
        o.z = fmaxf(fmaf(y.z, sc.z, sh.z), 0.f);
        o.w = fmaxf(fmaf(y.w, sc.w, sh.w), 0.f);
        *(float4*)&out[(size_t)(m0 + r) * F_OUT + ftile * 128 + c4] = o;
    }
}

extern "C" void kernel_launch(void* const* d_in, const int* in_sizes, int n_in,
                              void* d_out, int out_size) {
    const float* x     = (const float*)d_in[0];
    const float* W     = (const float*)d_in[1];
    // d_in[2] = conv bias b: cancels exactly under BatchNorm -> unused
    const float* gamma = (const float*)d_in[3];
    const float* beta  = (const float*)d_in[4];

    cudaFuncSetAttribute(fused_kernel, cudaFuncAttributeMaxDynamicSharedMemorySize, SM_TOT);

    wsplit_kernel<<<32, 256>>>(W);
    fused_kernel<<<dim3(2, MT), 256, SM_TOT>>>(x, gamma, beta, (float*)d_out);
}